// round 17
// baseline (speedup 1.0000x reference)
#include <cuda_runtime.h>
#include <cuda_fp16.h>
#include <cstddef>

// ---------------------------------------------------------------------------
// SAGE 2-layer. R14: single fused CSR kernel (hist -> scan -> scatter with
// grid rendezvous) + conversion/transpose rider blocks; memset graph nodes.
// GEMM: R13 ldmatrix fp16 path (unchanged).
// ---------------------------------------------------------------------------

static constexpr int cN0 = 200000;
static constexpr int cN1 = 50000;
static constexpr int cN2 = 10000;
static constexpr int cE1 = 1000000;
static constexpr int cE2 = 250000;
static constexpr int cCIN = 128;
static constexpr int cH = 256;

static constexpr int SCAN_CHUNK = 1024;
static constexpr int SB1 = (cN1 + 1 + SCAN_CHUNK - 1) / SCAN_CHUNK;  // 49
static constexpr int SB2 = (cN2 + 1 + SCAN_CHUNK - 1) / SCAN_CHUNK;  // 10

static constexpr int EPT  = 16;                                   // edges per thread
static constexpr int HB1  = (cE1 + 256 * EPT - 1) / (256 * EPT);  // 245
static constexpr int HB2  = (cE2 + 256 * EPT - 1) / (256 * EPT);  // 62
static constexpr int CSRB = HB1 + HB2;                            // 307 (co-resident at occ>=3)
static constexpr int NTR  = 2 * 32 + 2 * 64;                      // 192 transpose tiles
static constexpr int NCV  = (cN0 * cCIN) / (256 * 8);             // 12500 conv blocks

// ---- static device scratch ----
__device__ int    g_off1[cN1 + 1];
__device__ int    g_cur1[cN1];
__device__ int    g_adj1[cE1];
__device__ __half g_agg1[(size_t)cN1 * cCIN];
__device__ __half g_xh[(size_t)cN0 * cCIN];
__device__ __half g_h[(size_t)cN1 * cH];
__device__ int    g_off2[cN2 + 1];
__device__ int    g_cur2[cN2];
__device__ int    g_adj2[cE2];
__device__ __half g_agg2[(size_t)cN2 * cH];
__device__ int    g_parts[SB1 + SB2];
__device__ int    g_ctrs[3];            // rendezvous counters (memset to 0 per replay)
__device__ __half g_wl1t[cH * cCIN];    // transposed fp16 weights: wt[n*K+k] = W[k*N+n]
__device__ __half g_wr1t[cH * cCIN];
__device__ __half g_wl2t[cH * cH];
__device__ __half g_wr2t[cH * cH];

// ---------------------------------------------------------------------------
// grid rendezvous barrier (participating blocks must all be co-resident)
// ---------------------------------------------------------------------------
__device__ __forceinline__ void gbar(int* ctr, int target) {
    __syncthreads();
    if (threadIdx.x == 0) {
        __threadfence();
        atomicAdd(ctr, 1);
        while (*(volatile int*)ctr < target) __nanosleep(64);
        __threadfence();
    }
    __syncthreads();
}

// ---------------------------------------------------------------------------
// mega kernel helpers
// ---------------------------------------------------------------------------
__device__ __forceinline__ void hist_work(const int* __restrict__ dst, int E,
                                          int* __restrict__ off, int b) {
    int e0 = (b * 256 + threadIdx.x) * EPT;
    if (e0 + EPT <= E) {
        #pragma unroll
        for (int u = 0; u < EPT / 4; ++u) {
            int4 d = *(const int4*)(dst + e0 + 4 * u);
            atomicAdd(&off[d.x + 1], 1);
            atomicAdd(&off[d.y + 1], 1);
            atomicAdd(&off[d.z + 1], 1);
            atomicAdd(&off[d.w + 1], 1);
        }
    } else {
        for (int j = e0; j < E; ++j) atomicAdd(&off[dst[j] + 1], 1);
    }
}

__device__ __forceinline__ void scatter_work(const int* __restrict__ src,
                                             const int* __restrict__ dst, int E,
                                             int* __restrict__ cur, int* __restrict__ adj, int b) {
    int e0 = (b * 256 + threadIdx.x) * EPT;
    if (e0 + EPT <= E) {
        #pragma unroll
        for (int u = 0; u < EPT / 4; ++u) {
            int4 s = *(const int4*)(src + e0 + 4 * u);
            int4 d = *(const int4*)(dst + e0 + 4 * u);
            int p0 = atomicAdd(&cur[d.x], 1);
            int p1 = atomicAdd(&cur[d.y], 1);
            int p2 = atomicAdd(&cur[d.z], 1);
            int p3 = atomicAdd(&cur[d.w], 1);
            adj[p0] = s.x; adj[p1] = s.y; adj[p2] = s.z; adj[p3] = s.w;
        }
    } else {
        for (int j = e0; j < E; ++j) {
            int p = atomicAdd(&cur[dst[j]], 1);
            adj[p] = src[j];
        }
    }
}

__global__ void __launch_bounds__(256, 5)
k_mega(const int* __restrict__ src1, const int* __restrict__ dst1,
       const int* __restrict__ src2, const int* __restrict__ dst2,
       const float* __restrict__ x,
       const float* __restrict__ Wl1, const float* __restrict__ Wr1,
       const float* __restrict__ Wl2, const float* __restrict__ Wr2) {
    __shared__ int   wsum[8];
    __shared__ int   sprefix;
    __shared__ float tileS[32][33];

    int b = blockIdx.x;
    int tid = threadIdx.x;

    if (b < CSRB) {
        // ---------------- phase 1: histogram ----------------
        if (b < HB1) hist_work(dst1, cE1, g_off1, b);
        else         hist_work(dst2, cE2, g_off2, b - HB1);
        gbar(&g_ctrs[0], CSRB);

        // ---------------- phase 2: scan (first SB1+SB2 blocks) ----------------
        if (b < SB1 + SB2) {
            int* a; int n; int* cur; int ncur; int bb; int pbase;
            if (b < SB1) { a = g_off1; n = cN1 + 1; cur = g_cur1; ncur = cN1; bb = b;       pbase = 0; }
            else         { a = g_off2; n = cN2 + 1; cur = g_cur2; ncur = cN2; bb = b - SB1; pbase = SB1; }

            int lane = tid & 31, wid = tid >> 5;
            int i0 = bb * SCAN_CHUNK + tid * 4;

            int v0 = (i0 + 0 < n) ? a[i0 + 0] : 0;
            int v1 = (i0 + 1 < n) ? a[i0 + 1] : 0;
            int v2 = (i0 + 2 < n) ? a[i0 + 2] : 0;
            int v3 = (i0 + 3 < n) ? a[i0 + 3] : 0;
            int l1 = v0 + v1, l2 = l1 + v2, l3 = l2 + v3;

            int xs = l3;
            #pragma unroll
            for (int d = 1; d < 32; d <<= 1) {
                int t = __shfl_up_sync(0xffffffffu, xs, d);
                if (lane >= d) xs += t;
            }
            if (lane == 31) wsum[wid] = xs;
            __syncthreads();
            if (wid == 0 && lane < 8) {
                int s = wsum[lane];
                #pragma unroll
                for (int d = 1; d < 8; d <<= 1) {
                    int t = __shfl_up_sync(0x000000ffu, s, d);
                    if (lane >= d) s += t;
                }
                wsum[lane] = s;
            }
            __syncthreads();
            int pre = xs - l3 + (wid > 0 ? wsum[wid - 1] : 0);
            int o0 = pre + v0, o1 = pre + l1, o2 = pre + l2, o3 = pre + l3;

            if (tid == 255) g_parts[pbase + bb] = pre + l3;
            gbar(&g_ctrs[1], SB1 + SB2);   // internal rendezvous among scan blocks

            if (tid < 32) {
                int s = 0;
                for (int j = lane; j < bb; j += 32) s += g_parts[pbase + j];
                #pragma unroll
                for (int d = 16; d > 0; d >>= 1) s += __shfl_xor_sync(0xffffffffu, s, d);
                if (lane == 0) sprefix = s;
            }
            __syncthreads();
            int add = sprefix;
            o0 += add; o1 += add; o2 += add; o3 += add;
            if (i0 + 0 < n) a[i0 + 0] = o0;
            if (i0 + 1 < n) a[i0 + 1] = o1;
            if (i0 + 2 < n) a[i0 + 2] = o2;
            if (i0 + 3 < n) a[i0 + 3] = o3;
            if (i0 + 0 < ncur) cur[i0 + 0] = o0;
            if (i0 + 1 < ncur) cur[i0 + 1] = o1;
            if (i0 + 2 < ncur) cur[i0 + 2] = o2;
            if (i0 + 3 < ncur) cur[i0 + 3] = o3;
        }
        gbar(&g_ctrs[2], CSRB);

        // ---------------- phase 3: scatter ----------------
        if (b < HB1) scatter_work(src1, dst1, cE1, g_cur1, g_adj1, b);
        else         scatter_work(src2, dst2, cE2, g_cur2, g_adj2, b - HB1);
        return;
    }

    if (b < CSRB + NTR) {
        // ---------------- rider: weight transpose fp32 -> fp16 [n][k] ----------------
        const int NT1 = (cCIN / 32) * (cH / 32);   // 32
        const int NT2 = (cH / 32) * (cH / 32);     // 64
        int t = b - CSRB;
        const float* W; __half* wt; int K, tile;
        if      (t < NT1)           { W = Wl1; wt = g_wl1t; K = cCIN; tile = t; }
        else if (t < 2 * NT1)       { W = Wr1; wt = g_wr1t; K = cCIN; tile = t - NT1; }
        else if (t < 2 * NT1 + NT2) { W = Wl2; wt = g_wl2t; K = cH;   tile = t - 2 * NT1; }
        else                        { W = Wr2; wt = g_wr2t; K = cH;   tile = t - 2 * NT1 - NT2; }
        int ktiles = K / 32;
        int k0 = (tile % ktiles) * 32;
        int n0 = (tile / ktiles) * 32;
        int tx = tid & 31, ty = tid >> 5;   // 32 x 8
        #pragma unroll
        for (int i = 0; i < 4; ++i)
            tileS[ty + 8 * i][tx] = W[(size_t)(k0 + ty + 8 * i) * cH + n0 + tx];
        __syncthreads();
        #pragma unroll
        for (int i = 0; i < 4; ++i)
            wt[(size_t)(n0 + ty + 8 * i) * K + k0 + tx] = __float2half_rn(tileS[tx][ty + 8 * i]);
        return;
    }

    // ---------------- rider: x -> fp16 conversion ----------------
    {
        int cb = b - CSRB - NTR;
        int i = (cb * 256 + tid) * 8;
        const int nx = cN0 * cCIN;
        if (i + 8 <= nx) {
            float4 a = *(const float4*)(x + i);
            float4 c = *(const float4*)(x + i + 4);
            __half2 h0 = __floats2half2_rn(a.x, a.y);
            __half2 h1 = __floats2half2_rn(a.z, a.w);
            __half2 h2 = __floats2half2_rn(c.x, c.y);
            __half2 h3 = __floats2half2_rn(c.z, c.w);
            uint4 packed;
            packed.x = *(unsigned*)&h0; packed.y = *(unsigned*)&h1;
            packed.z = *(unsigned*)&h2; packed.w = *(unsigned*)&h3;
            *(uint4*)(g_xh + i) = packed;
        }
    }
}

// ---------------------------------------------------------------------------
// mean aggregation: fp16 in, fp32 accum, fp16 out.
// ---------------------------------------------------------------------------
template <int PL>
__global__ void k_agg_mean_h(const __half* __restrict__ feat, const int* __restrict__ adj,
                             const int* __restrict__ off, __half* __restrict__ out, int nrows) {
    int row = blockIdx.x * blockDim.y + threadIdx.y;
    if (row >= nrows) return;
    int lane = threadIdx.x;
    const int C = PL * 32;
    int s0 = off[row];
    int s1 = off[row + 1];

    float acc[PL];
    #pragma unroll
    for (int c = 0; c < PL; ++c) acc[c] = 0.f;

    auto accum_row = [&](int idx) {
        const __half* p = feat + (size_t)idx * C + lane * PL;
        if (PL == 8) {
            uint4 raw = *(const uint4*)p;
            const __half2* h = (const __half2*)&raw;
            #pragma unroll
            for (int j = 0; j < 4; ++j) {
                float2 f = __half22float2(h[j]);
                acc[2 * j] += f.x; acc[2 * j + 1] += f.y;
            }
        } else {
            uint2 raw = *(const uint2*)p;
            const __half2* h = (const __half2*)&raw;
            #pragma unroll
            for (int j = 0; j < 2; ++j) {
                float2 f = __half22float2(h[j]);
                acc[2 * j] += f.x; acc[2 * j + 1] += f.y;
            }
        }
    };

    int j = s0;
    for (; j + 4 <= s1; j += 4) {
        int i0 = adj[j], i1 = adj[j + 1], i2 = adj[j + 2], i3 = adj[j + 3];
        accum_row(i0); accum_row(i1); accum_row(i2); accum_row(i3);
    }
    for (; j < s1; ++j) accum_row(adj[j]);

    int deg = s1 - s0;
    float inv = 1.0f / (float)(deg > 0 ? deg : 1);
    __half* orow = out + (size_t)row * C + lane * PL;
    __half2 r[PL / 2];
    #pragma unroll
    for (int v = 0; v < PL / 2; ++v)
        r[v] = __floats2half2_rn(acc[2 * v] * inv, acc[2 * v + 1] * inv);
    if (PL == 8) *(uint4*)orow = *(uint4*)r;
    else         *(uint2*)orow = *(uint2*)r;
}

// ---------------------------------------------------------------------------
// fp16 GEMM with ldmatrix fragments, double-buffered, BK=32 (R13).
// ---------------------------------------------------------------------------
__device__ __forceinline__ void mma_f16(float* c, const unsigned* a, const unsigned* b) {
    asm volatile(
        "mma.sync.aligned.m16n8k16.row.col.f32.f16.f16.f32 "
        "{%0,%1,%2,%3}, {%4,%5,%6,%7}, {%8,%9}, {%0,%1,%2,%3};"
        : "+f"(c[0]), "+f"(c[1]), "+f"(c[2]), "+f"(c[3])
        : "r"(a[0]), "r"(a[1]), "r"(a[2]), "r"(a[3]), "r"(b[0]), "r"(b[1]));
}

__device__ __forceinline__ void ldsm_x4(unsigned* r, unsigned addr) {
    asm volatile("ldmatrix.sync.aligned.m8n8.x4.shared.b16 {%0,%1,%2,%3}, [%4];"
        : "=r"(r[0]), "=r"(r[1]), "=r"(r[2]), "=r"(r[3]) : "r"(addr));
}

__device__ __forceinline__ void store_pair(float* C, size_t off, float a, float b) {
    *(float2*)(C + off) = make_float2(a, b);
}
__device__ __forceinline__ void store_pair(__half* C, size_t off, float a, float b) {
    *(__half2*)(C + off) = __floats2half2_rn(a, b);
}

template <typename OutT>
__global__ void __launch_bounds__(256, 2)
k_gemm_dual_h(const __half* __restrict__ A1, const __half* __restrict__ A2,
              const __half* __restrict__ B1, const __half* __restrict__ B2,
              const float* __restrict__ bias, OutT* __restrict__ C,
              int M, int K1, int K2, int N, int doRelu) {
    __shared__ __align__(16) __half As[2][128 * 32];
    __shared__ __align__(16) __half Bs[2][128 * 32];

    int tid  = threadIdx.x;
    int lane = tid & 31;
    int warp = tid >> 5;
    int wm = warp >> 2;
    int wn = warp & 3;
    int g  = lane >> 2;
    int tg = lane & 3;
    int bm = blockIdx.y * 128;
    int bn = blockIdx.x * 128;
    int Ktot = K1 + K2;
    int ntiles = Ktot >> 5;

    float acc[4][4][4];
    #pragma unroll
    for (int mt = 0; mt < 4; ++mt)
        #pragma unroll
        for (int nt = 0; nt < 4; ++nt)
            #pragma unroll
            for (int c = 0; c < 4; ++c) acc[mt][nt][c] = 0.f;

    int sm = tid >> 1;
    int sh = tid & 1;
    int ssw = (sm >> 1) & 3;

    int mA  = (lane & 7) | (((lane >> 3) & 1) << 3);
    int kcA = (lane >> 4) & 1;
    int nB  = (lane & 7) | (((lane >> 4) & 1) << 3);
    int kcB = (lane >> 3) & 1;

    unsigned asAddr = (unsigned)__cvta_generic_to_shared(&As[0][0]);
    unsigned bsAddr = (unsigned)__cvta_generic_to_shared(&Bs[0][0]);

    uint4 avr0, avr1, bvr0, bvr1;

    auto ldg_tile = [&](int t) {
        int kb = t << 5;
        const __half *Asrc, *Bsrc; int ld, kcol;
        if (kb < K1) { Asrc = A1; Bsrc = B1; ld = K1; kcol = kb; }
        else         { Asrc = A2; Bsrc = B2; ld = K2; kcol = kb - K1; }
        int gm = bm + sm;
        if (gm < M) {
            const __half* ap = Asrc + (size_t)gm * ld + kcol + sh * 16;
            avr0 = *(const uint4*)ap;
            avr1 = *(const uint4*)(ap + 8);
        } else {
            avr0 = make_uint4(0, 0, 0, 0);
            avr1 = make_uint4(0, 0, 0, 0);
        }
        const __half* bp = Bsrc + (size_t)(bn + sm) * ld + kcol + sh * 16;
        bvr0 = *(const uint4*)bp;
        bvr1 = *(const uint4*)(bp + 8);
    };

    auto sts_tile = [&](int b) {
        int c0 = (2 * sh) ^ ssw;
        int c1 = (2 * sh + 1) ^ ssw;
        *(uint4*)&As[b][sm * 32 + c0 * 8] = avr0;
        *(uint4*)&As[b][sm * 32 + c1 * 8] = avr1;
        *(uint4*)&Bs[b][sm * 32 + c0 * 8] = bvr0;
        *(uint4*)&Bs[b][sm * 32 + c1 * 8] = bvr1;
    };

    auto compute_tile = [&](int b) {
        unsigned aB = asAddr + b * 8192;
        unsigned bB = bsAddr + b * 8192;
        #pragma unroll
        for (int kg = 0; kg < 2; ++kg) {
            unsigned af[4][4], bf[2][4];
            #pragma unroll
            for (int mt = 0; mt < 4; ++mt) {
                int m = wm * 64 + mt * 16 + mA;
                int ch = ((kg << 1) | kcA) ^ ((m >> 1) & 3);
                ldsm_x4(af[mt], aB + m * 64 + ch * 16);
            }
            #pragma unroll
            for (int p = 0; p < 2; ++p) {
                int n = wn * 32 + p * 16 + nB;
                int ch = ((kg << 1) | kcB) ^ ((n >> 1) & 3);
                ldsm_x4(bf[p], bB + n * 64 + ch * 16);
            }
            #pragma unroll
            for (int mt = 0; mt < 4; ++mt)
                #pragma unroll
                for (int nt = 0; nt < 4; ++nt)
                    mma_f16(acc[mt][nt], af[mt], &bf[nt >> 1][(nt & 1) << 1]);
        }
    };

    ldg_tile(0);
    sts_tile(0);
    __syncthreads();

    for (int t = 0; t < ntiles; ++t) {
        int cur = t & 1;
        if (t + 1 < ntiles) ldg_tile(t + 1);
        compute_tile(cur);
        if (t + 1 < ntiles) {
            sts_tile(cur ^ 1);
            __syncthreads();
        }
    }

    #pragma unroll
    for (int nt = 0; nt < 4; ++nt) {
        int col = bn + wn * 32 + nt * 8 + tg * 2;
        float2 bb = *(const float2*)&bias[col];
        #pragma unroll
        for (int mt = 0; mt < 4; ++mt) {
            int row_lo = bm + wm * 64 + mt * 16 + g;
            int row_hi = row_lo + 8;
            float lx = acc[mt][nt][0] + bb.x, ly = acc[mt][nt][1] + bb.y;
            float hx = acc[mt][nt][2] + bb.x, hy = acc[mt][nt][3] + bb.y;
            if (doRelu) {
                lx = fmaxf(lx, 0.f); ly = fmaxf(ly, 0.f);
                hx = fmaxf(hx, 0.f); hy = fmaxf(hy, 0.f);
            }
            if (row_lo < M) store_pair(C, (size_t)row_lo * N + col, lx, ly);
            if (row_hi < M) store_pair(C, (size_t)row_hi * N + col, hx, hy);
        }
    }
}

// ---------------------------------------------------------------------------
// host side
// ---------------------------------------------------------------------------
extern "C" void kernel_launch(void* const* d_in, const int* in_sizes, int n_in,
                              void* d_out, int out_size) {
    (void)in_sizes; (void)n_in; (void)out_size;

    const float* x    = (const float*)d_in[0];
    const int*   src1 = (const int*)d_in[1];
    const int*   dst1 = (const int*)d_in[2];
    const int*   src2 = (const int*)d_in[3];
    const int*   dst2 = (const int*)d_in[4];
    const float* Wl1  = (const float*)d_in[5];
    const float* Wr1  = (const float*)d_in[6];
    const float* b1   = (const float*)d_in[7];
    const float* Wl2  = (const float*)d_in[8];
    const float* Wr2  = (const float*)d_in[9];
    const float* b2   = (const float*)d_in[10];
    float* out = (float*)d_out;

    int *off1, *off2, *adj1, *adj2, *ctrs;
    __half *agg1, *agg2, *xh, *h, *wl1t, *wr1t, *wl2t, *wr2t;
    cudaGetSymbolAddress((void**)&off1, g_off1);
    cudaGetSymbolAddress((void**)&off2, g_off2);
    cudaGetSymbolAddress((void**)&adj1, g_adj1);
    cudaGetSymbolAddress((void**)&adj2, g_adj2);
    cudaGetSymbolAddress((void**)&ctrs, g_ctrs);
    cudaGetSymbolAddress((void**)&agg1, g_agg1);
    cudaGetSymbolAddress((void**)&agg2, g_agg2);
    cudaGetSymbolAddress((void**)&xh,   g_xh);
    cudaGetSymbolAddress((void**)&h,    g_h);
    cudaGetSymbolAddress((void**)&wl1t, g_wl1t);
    cudaGetSymbolAddress((void**)&wr1t, g_wr1t);
    cudaGetSymbolAddress((void**)&wl2t, g_wl2t);
    cudaGetSymbolAddress((void**)&wr2t, g_wr2t);

    // ---- zero off arrays + rendezvous counters (graph memset nodes) ----
    cudaMemsetAsync(off1, 0, (cN1 + 1) * sizeof(int));
    cudaMemsetAsync(off2, 0, (cN2 + 1) * sizeof(int));
    cudaMemsetAsync(ctrs, 0, 3 * sizeof(int));

    // ---- fused CSR build + conversion/transpose riders ----
    k_mega<<<CSRB + NTR + NCV, 256>>>(src1, dst1, src2, dst2, x, Wl1, Wr1, Wl2, Wr2);

    // ---- layer 1 ----
    k_agg_mean_h<4><<<(cN1 + 7) / 8, dim3(32, 8)>>>(xh, adj1, off1, agg1, cN1);
    k_gemm_dual_h<__half><<<dim3(cH / 128, (cN1 + 127) / 128), 256>>>(
        agg1, xh, wl1t, wr1t, b1, h, cN1, cCIN, cCIN, cH, 1);

    // ---- layer 2 ----
    k_agg_mean_h<8><<<(cN2 + 7) / 8, dim3(32, 8)>>>(h, adj2, off2, agg2, cN2);
    k_gemm_dual_h<float><<<dim3(cH / 128, (cN2 + 127) / 128), 256>>>(
        agg2, h, wl2t, wr2t, b2, out, cN2, cH, cH, cH, 0);
}